// round 5
// baseline (speedup 1.0000x reference)
#include <cuda_runtime.h>
#include <cuda_bf16.h>

// Output layout: [Cm1, 1, R, NC+4] fp32, flat.
// row(c, r): elements [0, NC) = out_class[0, r, :] broadcast over c
//            elements [NC, NC+4) = box(c, r)
//
// box(c,r):  x,y,w,h = rois[0,r,:];  tx,ty,tw,th = out_regr[0, r, c*4 + {0..3}]
//   gx = rint(w*tx + x); gy = rint(h*ty + y)
//   gw = rint(w*exp(tw)); gh = rint(h*exp(th))
//   box = [gx/W, gy/H, (gx+gw)/W, (gy+gh)/H]

__global__ void __launch_bounds__(256)
bb_creation_vec4_kernel(const float* __restrict__ regr,   // [R, Cm1, 4]
                        const float* __restrict__ cls,    // [R, NC]
                        const float4* __restrict__ rois,  // [R] of float4
                        float* __restrict__ out,
                        int R, int Cm1, int NC,
                        float invW, float invH,
                        long long n4)
{
    long long t = (long long)blockIdx.x * blockDim.x + threadIdx.x;
    if (t >= n4) return;

    const int rowlen = NC + 4;                 // 85
    const long long perC = (long long)R * rowlen;
    long long base = t << 2;                   // first flat element of this float4

    int c    = (int)(base / perC);             // constant across the 4 lanes-elements
    int rem0 = (int)(base - (long long)c * perC);
    int r0   = rem0 / rowlen;
    int k0   = rem0 - r0 * rowlen;

    float v[4];
#pragma unroll
    for (int i = 0; i < 4; ++i) {
        int k = k0 + i;
        int r = r0;
        if (k >= rowlen) { k -= rowlen; ++r; } // k0+3 <= 87 < 2*85: single carry max
        if (k < NC) {
            v[i] = __ldg(&cls[(long long)r * NC + k]);
        } else {
            float4 roi = __ldg(&rois[r]);
            const float x = roi.x, y = roi.y, w = roi.z, h = roi.w;
            const float* rg = regr + ((long long)r * Cm1 + c) * 4;
            int comp = k - NC;
            float val;
            if (comp == 0) {
                val = rintf(fmaf(w, __ldg(rg + 0), x)) * invW;
            } else if (comp == 1) {
                val = rintf(fmaf(h, __ldg(rg + 1), y)) * invH;
            } else if (comp == 2) {
                float gx = rintf(fmaf(w, __ldg(rg + 0), x));
                float gw = rintf(w * expf(__ldg(rg + 2)));
                val = (gx + gw) * invW;
            } else {
                float gy = rintf(fmaf(h, __ldg(rg + 1), y));
                float gh = rintf(h * expf(__ldg(rg + 3)));
                val = (gy + gh) * invH;
            }
            v[i] = val;
        }
    }

    float4 o;
    o.x = v[0]; o.y = v[1]; o.z = v[2]; o.w = v[3];
    reinterpret_cast<float4*>(out)[t] = o;
}

// Scalar tail (only used if out_size % 4 != 0 — not expected for these shapes,
// but kept for safety).
__global__ void __launch_bounds__(128)
bb_creation_tail_kernel(const float* __restrict__ regr,
                        const float* __restrict__ cls,
                        const float4* __restrict__ rois,
                        float* __restrict__ out,
                        int R, int Cm1, int NC,
                        float invW, float invH,
                        long long start, long long total)
{
    long long idx = start + blockIdx.x * blockDim.x + threadIdx.x;
    if (idx >= total) return;
    const int rowlen = NC + 4;
    const long long perC = (long long)R * rowlen;
    int c   = (int)(idx / perC);
    int rem = (int)(idx - (long long)c * perC);
    int r   = rem / rowlen;
    int k   = rem - r * rowlen;
    float val;
    if (k < NC) {
        val = cls[(long long)r * NC + k];
    } else {
        float4 roi = __ldg(&rois[r]);
        const float x = roi.x, y = roi.y, w = roi.z, h = roi.w;
        const float* rg = regr + ((long long)r * Cm1 + c) * 4;
        int comp = k - NC;
        if (comp == 0)      val = rintf(fmaf(w, rg[0], x)) * invW;
        else if (comp == 1) val = rintf(fmaf(h, rg[1], y)) * invH;
        else if (comp == 2) val = (rintf(fmaf(w, rg[0], x)) + rintf(w * expf(rg[2]))) * invW;
        else                val = (rintf(fmaf(h, rg[1], y)) + rintf(h * expf(rg[3]))) * invH;
    }
    out[idx] = val;
}

extern "C" void kernel_launch(void* const* d_in, const int* in_sizes, int n_in,
                              void* d_out, int out_size)
{
    const float*  regr = (const float*)d_in[0];   // [1, R, 4*Cm1]
    const float*  cls  = (const float*)d_in[1];   // [1, R, NC]
    const float4* rois = (const float4*)d_in[2];  // [1, R, 4]
    // d_in[3] = b: [1, H, W, 3] — only shape used. Assume square image.

    const int R   = in_sizes[2] / 4;
    const int Cm1 = in_sizes[0] / (R * 4);
    const int NC  = in_sizes[1] / R;              // 81

    // H = W = isqrt(b_elems / 3)
    long long hw = (long long)in_sizes[3] / 3;
    int side = 1;
    while ((long long)(side + 1) * (side + 1) <= hw) ++side;
    const float invW = 1.0f / (float)side;
    const float invH = 1.0f / (float)side;

    float* out = (float*)d_out;
    const long long total = (long long)out_size;
    const long long n4 = total >> 2;

    if (n4 > 0) {
        const int threads = 256;
        long long blocks = (n4 + threads - 1) / threads;
        bb_creation_vec4_kernel<<<(unsigned)blocks, threads>>>(
            regr, cls, rois, out, R, Cm1, NC, invW, invH, n4);
    }
    const long long done = n4 << 2;
    if (done < total) {
        long long rem = total - done;
        bb_creation_tail_kernel<<<(unsigned)((rem + 127) / 128), 128>>>(
            regr, cls, rois, out, R, Cm1, NC, invW, invH, done, total);
    }
}

// round 6
// speedup vs baseline: 1.7841x; 1.7841x over previous
#include <cuda_runtime.h>
#include <cuda_bf16.h>

// Output: [Cm1, 1, R, NC+4] fp32 flat.  rowlen = NC+4 (85), NC = 81.
//
// Two-phase plan:
//   Kernel A: branchless float4 broadcast of cls into the whole output
//             (box slots receive garbage cls bytes).
//   Kernel B: overwrite the 4 box elements of every (c, r) row.
// Same stream => A precedes B in the captured graph.

// ---------------- Kernel A: cls broadcast, 1 float4 per thread ----------------
// For output float4 #t within class c (element offset rem0 = 4t):
//   r  = rem0 / rowlen,  k0 = rem0 - r*rowlen
//   if k0 <= rowlen-4 : cls float4 index = t - r        (uses NC = rowlen-4)
//   else (carry)      : cls float4 index = t - (r + 1)  (pre-carry lanes are
//                                                        box slots -> garbage OK)
// Clamp index for the single all-box float4 at the end of the last row.
__global__ void __launch_bounds__(256)
cls_broadcast_kernel(const float4* __restrict__ cls4,
                     float4* __restrict__ out4,
                     int perC4,          // rowlen*R/4 (float4s per class)
                     int rowlen,         // NC+4
                     int maxClsIdx)      // (NC*R - 4) / 4
{
    int t = blockIdx.x * 256 + threadIdx.x;
    if (t >= perC4) return;
    const int c = blockIdx.y;

    unsigned rem0 = (unsigned)t << 2;
    unsigned r  = rem0 / (unsigned)rowlen;          // const-div -> umulhi seq
    unsigned k0 = rem0 - r * (unsigned)rowlen;
    unsigned rr = r + (k0 >= (unsigned)(rowlen - 3));  // carry -> next row
    int idx = t - (int)rr;
    idx = min(idx, maxClsIdx);

    out4[(size_t)c * (size_t)perC4 + (size_t)t] = __ldg(&cls4[idx]);
}

// ---------------- Kernel B: box values, 1 thread per (c, r) ----------------
__global__ void __launch_bounds__(256)
box_kernel(const float4* __restrict__ regr4,   // [R, Cm1] of float4
           const float4* __restrict__ rois,    // [R] of float4
           float* __restrict__ out,
           int R, int Cm1, int NC,
           float invW, float invH)
{
    int r = blockIdx.x * 32 + threadIdx.x;     // blockDim.x == 32 (coalesced-ish)
    int c = blockIdx.y * blockDim.y + threadIdx.y;
    if (r >= R || c >= Cm1) return;

    float4 roi = __ldg(&rois[r]);              // x, y, w, h
    float4 tg  = __ldg(&regr4[(size_t)r * Cm1 + c]);  // tx, ty, tw, th

    float gx = rintf(fmaf(roi.z, tg.x, roi.x));
    float gy = rintf(fmaf(roi.w, tg.y, roi.y));
    float gw = rintf(roi.z * expf(tg.z));
    float gh = rintf(roi.w * expf(tg.w));

    float* o = out + ((size_t)c * R + r) * (size_t)(NC + 4) + NC;
    o[0] = gx * invW;
    o[1] = gy * invH;
    o[2] = (gx + gw) * invW;
    o[3] = (gy + gh) * invH;
}

// ---------------- Generic scalar fallback (shape safety net) ----------------
__global__ void __launch_bounds__(256)
bb_generic_kernel(const float* __restrict__ regr,
                  const float* __restrict__ cls,
                  const float4* __restrict__ rois,
                  float* __restrict__ out,
                  int R, int Cm1, int NC,
                  float invW, float invH,
                  long long total)
{
    long long idx = (long long)blockIdx.x * blockDim.x + threadIdx.x;
    long long stride = (long long)gridDim.x * blockDim.x;
    const int rowlen = NC + 4;
    const long long perC = (long long)R * rowlen;
    for (; idx < total; idx += stride) {
        int c   = (int)(idx / perC);
        int rem = (int)(idx - (long long)c * perC);
        int r   = rem / rowlen;
        int k   = rem - r * rowlen;
        float val;
        if (k < NC) {
            val = cls[(long long)r * NC + k];
        } else {
            float4 roi = __ldg(&rois[r]);
            const float* rg = regr + ((long long)r * Cm1 + c) * 4;
            int comp = k - NC;
            if (comp == 0)      val = rintf(fmaf(roi.z, rg[0], roi.x)) * invW;
            else if (comp == 1) val = rintf(fmaf(roi.w, rg[1], roi.y)) * invH;
            else if (comp == 2) val = (rintf(fmaf(roi.z, rg[0], roi.x)) +
                                       rintf(roi.z * expf(rg[2]))) * invW;
            else                val = (rintf(fmaf(roi.w, rg[1], roi.y)) +
                                       rintf(roi.w * expf(rg[3]))) * invH;
        }
        out[idx] = val;
    }
}

extern "C" void kernel_launch(void* const* d_in, const int* in_sizes, int n_in,
                              void* d_out, int out_size)
{
    const float*  regr = (const float*)d_in[0];   // [1, R, 4*Cm1]
    const float*  cls  = (const float*)d_in[1];   // [1, R, NC]
    const float4* rois = (const float4*)d_in[2];  // [1, R, 4]

    const int R   = in_sizes[2] / 4;
    const int Cm1 = in_sizes[0] / (R * 4);
    const int NC  = in_sizes[1] / R;              // 81
    const int rowlen = NC + 4;

    // H = W = isqrt(b_elems / 3) (square image)
    long long hw = (long long)in_sizes[3] / 3;
    int side = 1;
    while ((long long)(side + 1) * (side + 1) <= hw) ++side;
    const float invW = 1.0f / (float)side;
    const float invH = 1.0f / (float)side;

    float* out = (float*)d_out;
    const long long perC  = (long long)R * rowlen;
    const long long total = (long long)out_size;

    const bool fast = (perC % 4 == 0) &&
                      (((long long)R * NC) % 4 == 0) &&
                      (total == (long long)Cm1 * perC) &&
                      (R % 32 == 0);

    if (fast) {
        // A: broadcast cls into everything
        const int perC4 = (int)(perC >> 2);
        const int maxClsIdx = (int)(((long long)R * NC - 4) >> 2);
        dim3 gridA((perC4 + 255) / 256, Cm1);
        cls_broadcast_kernel<<<gridA, 256>>>(
            (const float4*)cls, (float4*)out, perC4, rowlen, maxClsIdx);

        // B: overwrite box slots
        dim3 blockB(32, 8);
        dim3 gridB(R / 32, (Cm1 + 7) / 8);
        box_kernel<<<gridB, blockB>>>(
            (const float4*)regr, rois, out, R, Cm1, NC, invW, invH);
    } else {
        long long blocks = (total + 255) / 256;
        if (blocks > 262144) blocks = 262144;
        bb_generic_kernel<<<(unsigned)blocks, 256>>>(
            regr, cls, rois, out, R, Cm1, NC, invW, invH, total);
    }
}